// round 15
// baseline (speedup 1.0000x reference)
#include <cuda_runtime.h>
#include <cuda_bf16.h>

// ---------------------------------------------------------------------------
// 2-layer GCN + linear classifier, using linearity of the aggregation:
//   k1: h1  = relu(Agg(x)  @ W1 + b1)
//   k2: out = relu(Agg(h1) @ W2 + b2) @ Wc + bc
// Agg(t)[n] = t[n]*inv[n]^2 + sum_{e: dst=n} t[src_e]*inv[src_e]*inv[n]
//
// R11/R12: block-cooperative epilogue. Previously each warp streamed the whole
//      16KB W through the smem crossbar per node (~128 crossbar-cyc/node,
//      the real L1 bottleneck). Now the 8 warps of a block jointly compute
//      the 8x64 @ 64x64 tile (warp w -> cols [8w,8w+8) for all 8 rows),
//      amortizing W reads 8 ways (~32 cyc/node). Same for the classifier.
//      (R12 = R11 resubmit after infra failure; tail-block hbuf zero-fill.)
// ---------------------------------------------------------------------------

#define MAXN 50176
#define MAXE 1200000
#define DIN 64

__device__ int   g_deg[MAXN];        // statically zero; reset in scan3 each run
__device__ float g_inv[MAXN];
__device__ int   g_off[MAXN + 1];
__device__ int   g_cur[MAXN];
__device__ int   g_bsum[256];
__device__ int2  g_edge[MAXE];       // {src, float-bits weight}
__device__ float g_B[MAXN * DIN];

// --------------------------- index width handling --------------------------
// If the edge buffer is int64 (values < 2^31), every odd 32-bit word is 0.

__device__ __forceinline__ int detect64(const int* __restrict__ w) {
    int lane = threadIdx.x & 31;
    int bad = 0;
    #pragma unroll
    for (int j = 0; j < 4; j++)
        if (w[1 + 2 * (lane * 4 + j)] != 0) bad = 1;
    return (__ballot_sync(0xffffffffu, bad) == 0u);
}

__device__ __forceinline__ int load_idx(const int* p, long i, int is64) {
    if (is64) return (int)((const long long*)p)[i];
    return p[i];
}

// ------------------------------- CSR build ---------------------------------

__global__ void count_deg_k(const int* __restrict__ ei, int E) {
    int is64 = detect64(ei);
    int e = blockIdx.x * blockDim.x + threadIdx.x;
    if (e >= E) return;
    int d = load_idx(ei, (long)E + e, is64);
    atomicAdd(&g_deg[d], 1);
}

// coalesced block-local inclusive scan of deg; also finalizes g_inv.
__global__ __launch_bounds__(1024) void scan1_k(int n) {
    __shared__ int s[1024];
    int i = blockIdx.x * 1024 + threadIdx.x;
    int v = (i < n) ? g_deg[i] : 0;
    if (i < n) g_inv[i] = rsqrtf((float)(v + 1));
    s[threadIdx.x] = v;
    __syncthreads();
    #pragma unroll
    for (int d = 1; d < 1024; d <<= 1) {
        int t = (threadIdx.x >= d) ? s[threadIdx.x - d] : 0;
        __syncthreads();
        s[threadIdx.x] += t;
        __syncthreads();
    }
    if (i < n) g_off[i] = s[threadIdx.x];        // inclusive (temp)
    if (threadIdx.x == 1023) g_bsum[blockIdx.x] = s[1023];
}

// warp-parallel exclusive scan of up to 64 block sums (nb = 49 here).
__global__ void scan2_k(int nb) {
    int lane = threadIdx.x;
    int v0 = (lane < nb)      ? g_bsum[lane]      : 0;
    int v1 = (lane + 32 < nb) ? g_bsum[lane + 32] : 0;
    int s0 = v0, s1 = v1;
    #pragma unroll
    for (int d = 1; d < 32; d <<= 1) {
        int t0 = __shfl_up_sync(0xffffffffu, s0, d);
        int t1 = __shfl_up_sync(0xffffffffu, s1, d);
        if (lane >= d) { s0 += t0; s1 += t1; }
    }
    int tot0 = __shfl_sync(0xffffffffu, s0, 31);
    s1 += tot0;
    if (lane < nb)      g_bsum[lane]      = s0 - v0;
    if (lane + 32 < nb) g_bsum[lane + 32] = s1 - v1;
}

// finalize exclusive offsets, init cur, reset deg for next graph replay.
__global__ __launch_bounds__(1024) void scan3_k(int n, int E) {
    int i = blockIdx.x * 1024 + threadIdx.x;
    if (i == 0) g_off[n] = E;
    if (i >= n) return;
    int c = g_deg[i];
    int excl = g_off[i] - c + g_bsum[blockIdx.x];
    g_off[i] = excl;
    g_cur[i] = excl;
    g_deg[i] = 0;
}

__global__ void scatter_k(const int* __restrict__ ei, int E) {
    int is64 = detect64(ei);
    int e = blockIdx.x * blockDim.x + threadIdx.x;
    if (e >= E) return;
    int sN = load_idx(ei, e, is64);
    int d  = load_idx(ei, (long)E + e, is64);
    int pos = atomicAdd(&g_cur[d], 1);
    g_edge[pos] = make_int2(sN, __float_as_int(g_inv[sN] * g_inv[d]));
}

// ---------------------- aggregation + fused transform -----------------------
// Phase A (per warp): aggregate node's neighborhood; lane owns channels
//   {2*lane, 2*lane+1}; 32-edge smem stash broadcast; stash agg row in hbuf.
// Phase B (block-cooperative): H[8][64] = relu(hbuf @ W + b). Warp w computes
//   output cols [8w, 8w+8) for ALL 8 rows: lane -> (r = lane>>2, col pair
//   8w + 2*(lane&3)); W reads amortized 8x across warps.
// Phase C (STAGE 2): out[8][16] = H @ Wc + bc. Warp w owns row w.

#define HPAD 68   // hbuf row stride (words): 68 % 32 = 4 -> 8 rows hit 8 banks

template <int STAGE>
__global__ __launch_bounds__(256) void agg_mm_k(
    const float* __restrict__ T, const float* __restrict__ Wg,
    const float* __restrict__ bg, const float* __restrict__ Wcg,
    const float* __restrict__ bcg, float* __restrict__ Y, int n) {
    __shared__ __align__(16) float Ws[DIN * DIN];
    __shared__ __align__(16) float Wcs[DIN * 16];
    __shared__ __align__(16) float hbuf[8][HPAD];
    __shared__ __align__(16) float h2buf[8][HPAD];
    __shared__ __align__(16) int2  ebuf[8][32];

    int tid  = threadIdx.x;
    int wrp  = tid >> 5;
    int lane = tid & 31;

    for (int i = tid; i < DIN * DIN; i += 256) Ws[i] = Wg[i];
    if constexpr (STAGE == 2)
        for (int i = tid; i < DIN * 16; i += 256) Wcs[i] = Wcg[i];
    __syncthreads();

    int node = blockIdx.x * 8 + wrp;

    // ---- Phase A: aggregation ----
    if (node < n) {
        const float2* Tv = (const float2*)T;
        float invn = g_inv[node];
        float w0 = invn * invn;
        float2 sv = Tv[(long)node * 32 + lane];
        float accx = sv.x * w0, accy = sv.y * w0;

        int start = g_off[node];
        int cnt   = g_off[node + 1] - start;

        for (int base = 0; base < cnt; base += 32) {
            int j = base + lane;
            if (j < cnt) ebuf[wrp][lane] = g_edge[start + j];
            __syncwarp();
            int m = cnt - base; if (m > 32) m = 32;
            #pragma unroll 4
            for (int k = 0; k < m; k++) {
                int2 e = ebuf[wrp][k];
                float ww = __int_as_float(e.y);
                float2 hv = Tv[(long)e.x * 32 + lane];
                accx = fmaf(hv.x, ww, accx);
                accy = fmaf(hv.y, ww, accy);
            }
            __syncwarp();
        }
        hbuf[wrp][2 * lane]     = accx;
        hbuf[wrp][2 * lane + 1] = accy;
    } else {
        // tail block: keep Phase B reads defined
        hbuf[wrp][2 * lane]     = 0.0f;
        hbuf[wrp][2 * lane + 1] = 0.0f;
    }
    __syncthreads();

    // ---- Phase B: H = relu(hbuf @ W + b), block-cooperative ----
    int r  = lane >> 2;                 // row 0..7
    int oc = 8 * wrp + 2 * (lane & 3);  // this thread's 2 output cols
    float2 a = make_float2(0.f, 0.f);
    #pragma unroll
    for (int k = 0; k < DIN; k++) {
        float hk = hbuf[r][k];
        float2 wv = *(const float2*)&Ws[k * DIN + oc];
        a.x = fmaf(hk, wv.x, a.x);
        a.y = fmaf(hk, wv.y, a.y);
    }
    float2 bb = *(const float2*)&bg[oc];
    a.x = fmaxf(a.x + bb.x, 0.0f);
    a.y = fmaxf(a.y + bb.y, 0.0f);

    int node_r = blockIdx.x * 8 + r;

    if constexpr (STAGE == 1) {
        if (node_r < n)
            *(float2*)&Y[(long)node_r * DIN + oc] = a;
    } else {
        *(float2*)&h2buf[r][oc] = a;
        __syncthreads();

        // ---- Phase C: classifier, warp w owns row w ----
        if (node < n) {
            int o  = lane & 15;
            int k0 = (lane >> 4) * 32;
            float a2 = 0.f;
            #pragma unroll
            for (int k = 0; k < 32; k++)
                a2 = fmaf(h2buf[wrp][k0 + k], Wcs[(k0 + k) * 16 + o], a2);
            a2 += __shfl_down_sync(0xffffffffu, a2, 16);
            if (lane < 16)
                Y[(long)node * 16 + o] = a2 + bcg[o];
        }
    }
}

// --------------------------------- launch ----------------------------------

extern "C" void kernel_launch(void* const* d_in, const int* in_sizes, int n_in,
                              void* d_out, int out_size) {
    const float* x  = (const float*)d_in[0];
    const int*   ei = (const int*)d_in[1];
    const float* W1 = (const float*)d_in[2];
    const float* b1 = (const float*)d_in[3];
    const float* W2 = (const float*)d_in[4];
    const float* b2 = (const float*)d_in[5];
    const float* Wc = (const float*)d_in[6];
    const float* bc = (const float*)d_in[7];
    float* out = (float*)d_out;

    int n = in_sizes[0] / DIN;       // 50000
    int E = in_sizes[1] / 2;         // 800000

    float* B;
    cudaGetSymbolAddress((void**)&B, g_B);

    int tE = (E + 255) / 256;
    int nb = (n + 1023) / 1024;
    int agrid = (n + 7) / 8;

    count_deg_k<<<tE, 256>>>(ei, E);
    scan1_k<<<nb, 1024>>>(n);
    scan2_k<<<1, 32>>>(nb);
    scan3_k<<<nb, 1024>>>(n, E);
    scatter_k<<<tE, 256>>>(ei, E);
    agg_mm_k<1><<<agrid, 256>>>(x, W1, b1, nullptr, nullptr, B, n);
    agg_mm_k<2><<<agrid, 256>>>(B, W2, b2, Wc, bc, out, n);
}